// round 9
// baseline (speedup 1.0000x reference)
#include <cuda_runtime.h>
#include <cuda_bf16.h>
#include <cuda_fp8.h>
#include <cstdint>

// Problem dims (fixed by the dataset)
#define M_DIM 4096
#define N_DIM 4096
#define K_DIM 4096

// ---------------- scratch (device globals; no allocations allowed) ----------
// g_amax starts zero (BSS); atomicMax over identical inputs is idempotent
// across graph replays. g_cnt is reset to 0 by the combining CTA each run.
__device__ __align__(1024) __nv_bfloat16 g_dx[(size_t)M_DIM * K_DIM];
__device__ __align__(1024) __nv_bfloat16 g_dw[(size_t)N_DIM * K_DIM];
__device__ __align__(1024) float g_part[(size_t)2 * 1024 * 128 * 128];  // 128MB
__device__ int g_cnt[1024];
__device__ unsigned int g_amax[2];

// ---------------- PTX helpers ----------------------------------------------
__device__ __forceinline__ uint32_t smem_u32(const void* p) {
    uint32_t a;
    asm("{ .reg .u64 t; cvta.to.shared.u64 t, %1; cvt.u32.u64 %0, t; }"
        : "=r"(a) : "l"(p));
    return a;
}

#define CP16(dst, src) \
    asm volatile("cp.async.cg.shared.global [%0], [%1], 16;" :: "r"((uint32_t)(dst)), "l"(src) : "memory")
#define CP_COMMIT() asm volatile("cp.async.commit_group;" ::: "memory")
#define CP_WAIT1()  asm volatile("cp.async.wait_group 1;" ::: "memory")

__device__ __forceinline__ void ldsm4(uint32_t* r, uint32_t addr) {
    asm volatile("ldmatrix.sync.aligned.m8n8.x4.shared.b16 {%0,%1,%2,%3}, [%4];"
                 : "=r"(r[0]), "=r"(r[1]), "=r"(r[2]), "=r"(r[3]) : "r"(addr));
}

__device__ __forceinline__ void mma16816(float* d, const uint32_t* a, const uint32_t* b) {
    asm volatile(
        "mma.sync.aligned.m16n8k16.row.col.f32.bf16.bf16.f32 "
        "{%0,%1,%2,%3}, {%4,%5,%6,%7}, {%8,%9}, {%0,%1,%2,%3};"
        : "+f"(d[0]), "+f"(d[1]), "+f"(d[2]), "+f"(d[3])
        : "r"(a[0]), "r"(a[1]), "r"(a[2]), "r"(a[3]), "r"(b[0]), "r"(b[1]));
}

// ---------------- launch 0: global amax of BOTH tensors ---------------------
__global__ void k_amax2(const float* __restrict__ x, const float* __restrict__ w,
                        int n_each, int half) {
    int slot = (blockIdx.x >= half) ? 1 : 0;
    const float* p = slot ? w : x;
    int b = slot ? (blockIdx.x - half) : blockIdx.x;

    float m = 0.0f;
    int i = b * blockDim.x + threadIdx.x;
    int stride = half * blockDim.x;
    const float4* p4 = reinterpret_cast<const float4*>(p);
    int n4 = n_each >> 2;
    for (int j = i; j < n4; j += stride) {
        float4 v = p4[j];
        m = fmaxf(m, fmaxf(fmaxf(fabsf(v.x), fabsf(v.y)), fmaxf(fabsf(v.z), fabsf(v.w))));
    }
    #pragma unroll
    for (int o = 16; o > 0; o >>= 1)
        m = fmaxf(m, __shfl_xor_sync(0xFFFFFFFFu, m, o));
    if ((threadIdx.x & 31) == 0)
        atomicMax(&g_amax[slot], __float_as_uint(m));
}

// ---------------- launches 1,2: quantize->dequantize to bf16 ----------------
// One thread per 16-element NVFP4 block. Exact replication of reference math.
__global__ void __launch_bounds__(256) k_quant(const float* __restrict__ src, int slot) {
    __nv_bfloat16* __restrict__ dst = (slot == 0) ? g_dx : g_dw;
    float am = fmaxf(__uint_as_float(g_amax[slot]), 1e-12f);
    float gs = __fdiv_rn(2688.0f, am);          // QUANT_RANGE / amax (IEEE RN)
    size_t blk = (size_t)blockIdx.x * blockDim.x + threadIdx.x;

    const float4* s4 = reinterpret_cast<const float4*>(src) + blk * 4;
    float4 f0 = s4[0], f1 = s4[1], f2 = s4[2], f3 = s4[3];
    float v[16] = {f0.x, f0.y, f0.z, f0.w, f1.x, f1.y, f1.z, f1.w,
                   f2.x, f2.y, f2.z, f2.w, f3.x, f3.y, f3.z, f3.w};

    float bm = 0.0f;
    #pragma unroll
    for (int i = 0; i < 16; ++i) bm = fmaxf(bm, fabsf(v[i]));

    float t = __fdiv_rn(bm * gs, 6.0f);
    __nv_fp8_storage_t s8 = __nv_cvt_float_to_fp8(t, __NV_SATFINITE, __NV_E4M3);
    float sf = __half2float((__half)__nv_cvt_fp8_to_halfraw(s8, __NV_E4M3));
    float ratio = __fdiv_rn(gs, fmaxf(sf, 1e-12f));

    union { __nv_bfloat16 h[16]; uint4 u[2]; } pk;
    #pragma unroll
    for (int i = 0; i < 16; ++i) {
        float a = fabsf(v[i]) * ratio;
        float stp = (a < 2.0f) ? 0.5f : ((a < 4.0f) ? 1.0f : 2.0f);
        float inv = (a < 2.0f) ? 2.0f : ((a < 4.0f) ? 1.0f : 0.5f);
        float q = fminf(rintf(a * inv) * stp, 6.0f);  // RTNE, same grid as ref
        float dq = (v[i] < 0.0f ? -q : q) * sf;       // <=6 sig bits: exact in bf16
        pk.h[i] = __float2bfloat16(dq);
    }
    uint4* d = reinterpret_cast<uint4*>(dst + blk * 16);
    d[0] = pk.u[0];
    d[1] = pk.u[1];
}

// ---------------- launch 3: bf16 mma.sync GEMM, split-K=2 -------------------
// out[m,n] = alpha * sum_k dx[m,k]*dw[n,k] + bias[n]
// Tile 128x128x64, 128 threads (4 warps, warp tile 64x64), 3 stages,
// 2 CTAs/SM. Each tile is computed by 2 CTAs (K halves); the second CTA to
// finish combines both partials deterministically (fp add in RN is
// commutative bitwise, so the combined expression is order-independent).
#define TM 128
#define TN 128
#define TK 64
#define STAGES 3
#define THREADS 128
#define KHALF (K_DIM / 2)       // 2048
#define NKT (KHALF / TK)        // 32
#define A_STG (TM * TK * 2)     // 16384 B
#define B_STG (TN * TK * 2)     // 16384 B
#define STG   (A_STG + B_STG)   // 32768 B
#define SMEM_BYTES (STAGES * STG)   // 98304 -> 2 CTAs/SM
#define GJUMP ((size_t)16 * K_DIM * 2)   // 16 global rows between a thread's chunks

__global__ void __launch_bounds__(THREADS, 2) k_gemm(const float* __restrict__ bias,
                                                     float* __restrict__ out) {
    extern __shared__ char smem[];
    __shared__ int role;
    uint32_t sb = smem_u32(smem);

    int tid  = threadIdx.x;
    int wid  = tid >> 5;
    int lane = tid & 31;

    // bid -> (split, tile) ; split is the slow dimension so co-running CTAs
    // share the same K-half (L2 reuse). GROUP_M=8 raster within each half.
    int bid   = blockIdx.x;
    int split = bid >> 10;               // 0 or 1
    int tb    = bid & 1023;
    int g  = tb >> 8;                    // 4 groups of 256
    int r  = tb & 255;
    int mt = g * 8 + (r & 7);
    int nt = r >> 3;
    int m0 = mt * TM, n0 = nt * TN;
    int tile = mt * 32 + nt;

    int moff = (wid & 1) * 64;           // 2 warps in M
    int noff = (wid >> 1) * 64;          // 2 warps in N

    // ---- cp.async: 8 A + 8 B chunks per thread via row-stride-16 jumps -----
    int prow = tid >> 3;                 // 0..15
    int pc   = tid & 7;                  // 16B chunk in 128B row
    size_t ksplit = (size_t)split * KHALF * 2;   // byte offset of this K half
    const char* abase = (const char*)g_dx + ((size_t)(m0 + prow) * K_DIM + pc * 8) * 2 + ksplit;
    const char* bbase = (const char*)g_dw + ((size_t)(n0 + prow) * K_DIM + pc * 8) * 2 + ksplit;
    uint32_t asoff = (uint32_t)(prow * 128 + ((pc ^ (prow & 7)) << 4));
    uint32_t bsoff = asoff + A_STG;

    // ---- ldmatrix row bases -------------------------------------------------
    int a_rl = lane & 15;
    int a_ko = lane >> 4;
    int b_rl = (lane & 7) | ((lane >> 4) << 3);
    int b_ko = (lane >> 3) & 1;

    uint32_t arow[4]; int arx[4];
    #pragma unroll
    for (int t = 0; t < 4; ++t) {
        int rr = moff + t * 16 + a_rl;
        arow[t] = (uint32_t)(rr * 128);
        arx[t]  = rr & 7;
    }
    uint32_t brow[4]; int brx[4];
    #pragma unroll
    for (int t = 0; t < 4; ++t) {
        int rr = noff + t * 16 + b_rl;
        brow[t] = (uint32_t)(rr * 128 + A_STG);
        brx[t]  = rr & 7;
    }

    float acc[4][8][4];                  // [m16][n8][frag] = 128 regs
    #pragma unroll
    for (int i = 0; i < 4; ++i)
        #pragma unroll
        for (int j = 0; j < 8; ++j)
            #pragma unroll
            for (int q = 0; q < 4; ++q) acc[i][j][q] = 0.0f;

    // ---- prologue: fill stages 0,1 -----------------------------------------
    #pragma unroll
    for (int p = 0; p < STAGES - 1; ++p) {
        size_t koff = (size_t)p * 128;   // TK*2 bytes within this K half
        uint32_t d0 = sb + p * STG;
        #pragma unroll
        for (int j = 0; j < 8; ++j) CP16(d0 + asoff + j * 2048, abase + j * GJUMP + koff);
        #pragma unroll
        for (int j = 0; j < 8; ++j) CP16(d0 + bsoff + j * 2048, bbase + j * GJUMP + koff);
        CP_COMMIT();
    }

    int s_use = 0, s_pf = STAGES - 1;
    for (int kt = 0; kt < NKT; ++kt) {
        CP_WAIT1();
        __syncthreads();

        int pf = kt + STAGES - 1;
        bool do_pf = (pf < NKT);
        size_t koff = (size_t)pf * 128;
        uint32_t d0 = sb + s_pf * STG;
        uint32_t bA = sb + s_use * STG;

        // ks blocks with cp.async interleaved into the ldsm->mma latency gap:
        // ks0 issues A chunks 0-3, ks1 A chunks 4-7, ks2 B 0-3, ks3 B 4-7.
        #pragma unroll
        for (int ks = 0; ks < 4; ++ks) {
            uint32_t a[4][4], b[4][4];
            #pragma unroll
            for (int t = 0; t < 4; ++t)
                ldsm4(a[t], bA + arow[t] + (uint32_t)((((ks * 2 + a_ko) ^ arx[t])) << 4));
            #pragma unroll
            for (int t = 0; t < 4; ++t)
                ldsm4(b[t], bA + brow[t] + (uint32_t)((((ks * 2 + b_ko) ^ brx[t])) << 4));

            if (do_pf) {
                if (ks < 2) {
                    #pragma unroll
                    for (int j = 0; j < 4; ++j) {
                        int c = ks * 4 + j;
                        CP16(d0 + asoff + c * 2048, abase + c * GJUMP + koff);
                    }
                } else {
                    #pragma unroll
                    for (int j = 0; j < 4; ++j) {
                        int c = (ks - 2) * 4 + j;
                        CP16(d0 + bsoff + c * 2048, bbase + c * GJUMP + koff);
                    }
                }
            }

            #pragma unroll
            for (int i = 0; i < 4; ++i)
                #pragma unroll
                for (int j = 0; j < 8; ++j)
                    mma16816(acc[i][j], a[i], &b[j >> 1][(j & 1) * 2]);
        }
        CP_COMMIT();                     // always commit (keeps wait_group count)

        if (++s_use == STAGES) s_use = 0;
        if (++s_pf  == STAGES) s_pf  = 0;
    }

    // ---- split-K combine -----------------------------------------------------
    // 1) store my partial to scratch slot (tile, split), coalesced per (i,j)
    float* myslot = g_part + ((size_t)tile * 2 + split) * (TM * TN);
    #pragma unroll
    for (int i = 0; i < 4; ++i)
        #pragma unroll
        for (int j = 0; j < 8; ++j) {
            float4 p = {acc[i][j][0], acc[i][j][1], acc[i][j][2], acc[i][j][3]};
            *reinterpret_cast<float4*>(myslot + (i * 8 + j) * 512 + tid * 4) = p;
        }
    __threadfence();
    __syncthreads();
    if (tid == 0) role = atomicAdd(&g_cnt[tile], 1);
    __syncthreads();
    if (role == 0) return;               // first finisher: partial published
    if (tid == 0) g_cnt[tile] = 0;       // reset for the next graph replay
    __threadfence();                     // order partner-slot loads after atomic

    // 2) second finisher: combine both partials and write the output
    const float* oslot = g_part + ((size_t)tile * 2 + (1 - split)) * (TM * TN);
    float ax = fmaxf(__uint_as_float(g_amax[0]), 1e-12f);
    float aw = fmaxf(__uint_as_float(g_amax[1]), 1e-12f);
    float alpha = __fdiv_rn(ax * aw, 7225344.0f);  // QUANT_RANGE^2
    int er = lane >> 2;
    int c2 = (lane & 3) * 2;
    float bcache[8][2];
    #pragma unroll
    for (int j = 0; j < 8; ++j) {
        bcache[j][0] = bias[n0 + noff + j * 8 + c2];
        bcache[j][1] = bias[n0 + noff + j * 8 + c2 + 1];
    }
    #pragma unroll
    for (int i = 0; i < 4; ++i) {
        int gm = m0 + moff + i * 16 + er;
        float* row0 = out + (size_t)gm * N_DIM + n0 + noff;
        float* row1 = row0 + (size_t)8 * N_DIM;
        #pragma unroll
        for (int j = 0; j < 8; ++j) {
            float4 oth = *reinterpret_cast<const float4*>(oslot + (i * 8 + j) * 512 + tid * 4);
            // fp add (RN) is commutative bitwise -> deterministic either way
            float sx = acc[i][j][0] + oth.x;
            float sy = acc[i][j][1] + oth.y;
            float sz = acc[i][j][2] + oth.z;
            float sw = acc[i][j][3] + oth.w;
            int col = j * 8 + c2;
            float2 v0 = {alpha * sx + bcache[j][0], alpha * sy + bcache[j][1]};
            float2 v1 = {alpha * sz + bcache[j][0], alpha * sw + bcache[j][1]};
            *reinterpret_cast<float2*>(row0 + col) = v0;
            *reinterpret_cast<float2*>(row1 + col) = v1;
        }
    }
}

// ---------------- launcher ---------------------------------------------------
// Exactly 4 launches; k_gemm at launch index 3 (the slot ncu captures).
extern "C" void kernel_launch(void* const* d_in, const int* in_sizes, int n_in,
                              void* d_out, int out_size) {
    const float* x    = (const float*)d_in[0];
    const float* w    = (const float*)d_in[1];
    const float* bias = (const float*)d_in[2];
    float* out        = (float*)d_out;
    int nx = in_sizes[0];

    cudaFuncSetAttribute(k_gemm, cudaFuncAttributeMaxDynamicSharedMemorySize, SMEM_BYTES);
    cudaFuncSetAttribute(k_gemm, cudaFuncAttributePreferredSharedMemoryCarveout,
                         cudaSharedmemCarveoutMaxShared);

    k_amax2<<<2048, 256>>>(x, w, nx, 1024);                 // launch 0
    k_quant<<<(M_DIM * K_DIM / 16) / 256, 256>>>(x, 0);     // launch 1
    k_quant<<<(N_DIM * K_DIM / 16) / 256, 256>>>(w, 1);     // launch 2

    int grid = 2 * (M_DIM / TM) * (N_DIM / TN);   // 2048 (split-K=2)
    k_gemm<<<grid, THREADS, SMEM_BYTES>>>(bias, out);       // launch 3
}

// round 10
// speedup vs baseline: 1.0269x; 1.0269x over previous
#include <cuda_runtime.h>
#include <cuda_bf16.h>
#include <cuda_fp8.h>
#include <cstdint>

// Problem dims (fixed by the dataset)
#define M_DIM 4096
#define N_DIM 4096
#define K_DIM 4096

// ---------------- scratch (device globals; no allocations allowed) ----------
// g_amax starts zero (BSS); atomicMax over identical inputs is idempotent
// across graph replays. g_cnt is reset to 0 by the combining CTA each run.
__device__ __align__(1024) __nv_bfloat16 g_dx[(size_t)M_DIM * K_DIM];
__device__ __align__(1024) __nv_bfloat16 g_dw[(size_t)N_DIM * K_DIM];
__device__ __align__(1024) float g_part[(size_t)2 * 1024 * 128 * 128];  // 128MB
__device__ int g_cnt[1024];
__device__ unsigned int g_amax[2];

// ---------------- PTX helpers ----------------------------------------------
__device__ __forceinline__ uint32_t smem_u32(const void* p) {
    uint32_t a;
    asm("{ .reg .u64 t; cvta.to.shared.u64 t, %1; cvt.u32.u64 %0, t; }"
        : "=r"(a) : "l"(p));
    return a;
}

#define CP16(dst, src) \
    asm volatile("cp.async.cg.shared.global [%0], [%1], 16;" :: "r"((uint32_t)(dst)), "l"(src) : "memory")
#define CP_COMMIT() asm volatile("cp.async.commit_group;" ::: "memory")
#define CP_WAIT1()  asm volatile("cp.async.wait_group 1;" ::: "memory")

__device__ __forceinline__ void ldsm4(uint32_t* r, uint32_t addr) {
    asm volatile("ldmatrix.sync.aligned.m8n8.x4.shared.b16 {%0,%1,%2,%3}, [%4];"
                 : "=r"(r[0]), "=r"(r[1]), "=r"(r[2]), "=r"(r[3]) : "r"(addr));
}

__device__ __forceinline__ void mma16816(float* d, const uint32_t* a, const uint32_t* b) {
    asm volatile(
        "mma.sync.aligned.m16n8k16.row.col.f32.bf16.bf16.f32 "
        "{%0,%1,%2,%3}, {%4,%5,%6,%7}, {%8,%9}, {%0,%1,%2,%3};"
        : "+f"(d[0]), "+f"(d[1]), "+f"(d[2]), "+f"(d[3])
        : "r"(a[0]), "r"(a[1]), "r"(a[2]), "r"(a[3]), "r"(b[0]), "r"(b[1]));
}

// ---------------- launch 0: global amax of BOTH tensors ---------------------
__global__ void k_amax2(const float* __restrict__ x, const float* __restrict__ w,
                        int n_each, int half) {
    int slot = (blockIdx.x >= half) ? 1 : 0;
    const float* p = slot ? w : x;
    int b = slot ? (blockIdx.x - half) : blockIdx.x;

    float m = 0.0f;
    int i = b * blockDim.x + threadIdx.x;
    int stride = half * blockDim.x;
    const float4* p4 = reinterpret_cast<const float4*>(p);
    int n4 = n_each >> 2;
    for (int j = i; j < n4; j += stride) {
        float4 v = p4[j];
        m = fmaxf(m, fmaxf(fmaxf(fabsf(v.x), fabsf(v.y)), fmaxf(fabsf(v.z), fabsf(v.w))));
    }
    #pragma unroll
    for (int o = 16; o > 0; o >>= 1)
        m = fmaxf(m, __shfl_xor_sync(0xFFFFFFFFu, m, o));
    if ((threadIdx.x & 31) == 0)
        atomicMax(&g_amax[slot], __float_as_uint(m));
}

// ---------------- launches 1,2: quantize->dequantize to bf16 ----------------
// One thread per 16-element NVFP4 block. Exact replication of reference math.
__global__ void __launch_bounds__(256) k_quant(const float* __restrict__ src, int slot) {
    __nv_bfloat16* __restrict__ dst = (slot == 0) ? g_dx : g_dw;
    float am = fmaxf(__uint_as_float(g_amax[slot]), 1e-12f);
    float gs = __fdiv_rn(2688.0f, am);          // QUANT_RANGE / amax (IEEE RN)
    size_t blk = (size_t)blockIdx.x * blockDim.x + threadIdx.x;

    const float4* s4 = reinterpret_cast<const float4*>(src) + blk * 4;
    float4 f0 = s4[0], f1 = s4[1], f2 = s4[2], f3 = s4[3];
    float v[16] = {f0.x, f0.y, f0.z, f0.w, f1.x, f1.y, f1.z, f1.w,
                   f2.x, f2.y, f2.z, f2.w, f3.x, f3.y, f3.z, f3.w};

    float bm = 0.0f;
    #pragma unroll
    for (int i = 0; i < 16; ++i) bm = fmaxf(bm, fabsf(v[i]));

    float t = __fdiv_rn(bm * gs, 6.0f);
    __nv_fp8_storage_t s8 = __nv_cvt_float_to_fp8(t, __NV_SATFINITE, __NV_E4M3);
    float sf = __half2float((__half)__nv_cvt_fp8_to_halfraw(s8, __NV_E4M3));
    float ratio = __fdiv_rn(gs, fmaxf(sf, 1e-12f));

    union { __nv_bfloat16 h[16]; uint4 u[2]; } pk;
    #pragma unroll
    for (int i = 0; i < 16; ++i) {
        float a = fabsf(v[i]) * ratio;
        float stp = (a < 2.0f) ? 0.5f : ((a < 4.0f) ? 1.0f : 2.0f);
        float inv = (a < 2.0f) ? 2.0f : ((a < 4.0f) ? 1.0f : 0.5f);
        float q = fminf(rintf(a * inv) * stp, 6.0f);  // RTNE, same grid as ref
        float dq = (v[i] < 0.0f ? -q : q) * sf;       // <=6 sig bits: exact in bf16
        pk.h[i] = __float2bfloat16(dq);
    }
    uint4* d = reinterpret_cast<uint4*>(dst + blk * 16);
    d[0] = pk.u[0];
    d[1] = pk.u[1];
}

// ---------------- launch 3: bf16 mma.sync GEMM, split-K=2 -------------------
// out[m,n] = alpha * sum_k dx[m,k]*dw[n,k] + bias[n]
// Tile 128x128x64, 128 threads (4 warps, warp tile 64x64), 3 stages,
// 2 CTAs/SM. Each tile is computed by 2 CTAs (K halves) with ADJACENT block
// ids, so the pair is co-scheduled: combines are spread uniformly over the
// kernel and the partner partial is L2-hot. The second CTA to finish combines
// both partials deterministically (fp add in RN is commutative bitwise).
#define TM 128
#define TN 128
#define TK 64
#define STAGES 3
#define THREADS 128
#define KHALF (K_DIM / 2)       // 2048
#define NKT (KHALF / TK)        // 32
#define A_STG (TM * TK * 2)     // 16384 B
#define B_STG (TN * TK * 2)     // 16384 B
#define STG   (A_STG + B_STG)   // 32768 B
#define SMEM_BYTES (STAGES * STG)   // 98304 -> 2 CTAs/SM
#define GJUMP ((size_t)16 * K_DIM * 2)   // 16 global rows between a thread's chunks

__global__ void __launch_bounds__(THREADS, 2) k_gemm(const float* __restrict__ bias,
                                                     float* __restrict__ out) {
    extern __shared__ char smem[];
    __shared__ int role;
    uint32_t sb = smem_u32(smem);

    int tid  = threadIdx.x;
    int wid  = tid >> 5;
    int lane = tid & 31;

    // bid -> (tile, split); split is the FAST dimension so the two CTAs of a
    // tile are adjacent -> co-scheduled -> combine overlap + L2-hot partner.
    int bid   = blockIdx.x;
    int split = bid & 1;
    int tb    = bid >> 1;                // 0..1023
    int g  = tb >> 8;                    // 4 groups of 256 (GROUP_M=8 raster)
    int r  = tb & 255;
    int mt = g * 8 + (r & 7);
    int nt = r >> 3;
    int m0 = mt * TM, n0 = nt * TN;
    int tile = mt * 32 + nt;

    int moff = (wid & 1) * 64;           // 2 warps in M
    int noff = (wid >> 1) * 64;          // 2 warps in N

    // ---- cp.async: 8 A + 8 B chunks per thread via row-stride-16 jumps -----
    int prow = tid >> 3;                 // 0..15
    int pc   = tid & 7;                  // 16B chunk in 128B row
    size_t ksplit = (size_t)split * KHALF * 2;   // byte offset of this K half
    const char* abase = (const char*)g_dx + ((size_t)(m0 + prow) * K_DIM + pc * 8) * 2 + ksplit;
    const char* bbase = (const char*)g_dw + ((size_t)(n0 + prow) * K_DIM + pc * 8) * 2 + ksplit;
    uint32_t asoff = (uint32_t)(prow * 128 + ((pc ^ (prow & 7)) << 4));
    uint32_t bsoff = asoff + A_STG;

    // ---- ldmatrix row bases -------------------------------------------------
    int a_rl = lane & 15;
    int a_ko = lane >> 4;
    int b_rl = (lane & 7) | ((lane >> 4) << 3);
    int b_ko = (lane >> 3) & 1;

    uint32_t arow[4]; int arx[4];
    #pragma unroll
    for (int t = 0; t < 4; ++t) {
        int rr = moff + t * 16 + a_rl;
        arow[t] = (uint32_t)(rr * 128);
        arx[t]  = rr & 7;
    }
    uint32_t brow[4]; int brx[4];
    #pragma unroll
    for (int t = 0; t < 4; ++t) {
        int rr = noff + t * 16 + b_rl;
        brow[t] = (uint32_t)(rr * 128 + A_STG);
        brx[t]  = rr & 7;
    }

    float acc[4][8][4];                  // [m16][n8][frag] = 128 regs
    #pragma unroll
    for (int i = 0; i < 4; ++i)
        #pragma unroll
        for (int j = 0; j < 8; ++j)
            #pragma unroll
            for (int q = 0; q < 4; ++q) acc[i][j][q] = 0.0f;

    // ---- prologue: fill stages 0,1 -----------------------------------------
    #pragma unroll
    for (int p = 0; p < STAGES - 1; ++p) {
        size_t koff = (size_t)p * 128;   // TK*2 bytes within this K half
        uint32_t d0 = sb + p * STG;
        #pragma unroll
        for (int j = 0; j < 8; ++j) CP16(d0 + asoff + j * 2048, abase + j * GJUMP + koff);
        #pragma unroll
        for (int j = 0; j < 8; ++j) CP16(d0 + bsoff + j * 2048, bbase + j * GJUMP + koff);
        CP_COMMIT();
    }

    int s_use = 0, s_pf = STAGES - 1;
    for (int kt = 0; kt < NKT; ++kt) {
        CP_WAIT1();
        __syncthreads();

        int pf = kt + STAGES - 1;
        bool do_pf = (pf < NKT);
        size_t koff = (size_t)pf * 128;
        uint32_t d0 = sb + s_pf * STG;
        uint32_t bA = sb + s_use * STG;

        // ks blocks with cp.async interleaved into the ldsm->mma latency gap:
        // ks0 issues A chunks 0-3, ks1 A chunks 4-7, ks2 B 0-3, ks3 B 4-7.
        #pragma unroll
        for (int ks = 0; ks < 4; ++ks) {
            uint32_t a[4][4], b[4][4];
            #pragma unroll
            for (int t = 0; t < 4; ++t)
                ldsm4(a[t], bA + arow[t] + (uint32_t)((((ks * 2 + a_ko) ^ arx[t])) << 4));
            #pragma unroll
            for (int t = 0; t < 4; ++t)
                ldsm4(b[t], bA + brow[t] + (uint32_t)((((ks * 2 + b_ko) ^ brx[t])) << 4));

            if (do_pf) {
                if (ks < 2) {
                    #pragma unroll
                    for (int j = 0; j < 4; ++j) {
                        int c = ks * 4 + j;
                        CP16(d0 + asoff + c * 2048, abase + c * GJUMP + koff);
                    }
                } else {
                    #pragma unroll
                    for (int j = 0; j < 4; ++j) {
                        int c = (ks - 2) * 4 + j;
                        CP16(d0 + bsoff + c * 2048, bbase + c * GJUMP + koff);
                    }
                }
            }

            #pragma unroll
            for (int i = 0; i < 4; ++i)
                #pragma unroll
                for (int j = 0; j < 8; ++j)
                    mma16816(acc[i][j], a[i], &b[j >> 1][(j & 1) * 2]);
        }
        CP_COMMIT();                     // always commit (keeps wait_group count)

        if (++s_use == STAGES) s_use = 0;
        if (++s_pf  == STAGES) s_pf  = 0;
    }

    // ---- split-K combine -----------------------------------------------------
    // 1) store my partial to scratch slot (tile, split), coalesced per (i,j)
    float* myslot = g_part + ((size_t)tile * 2 + split) * (TM * TN);
    #pragma unroll
    for (int i = 0; i < 4; ++i)
        #pragma unroll
        for (int j = 0; j < 8; ++j) {
            float4 p = {acc[i][j][0], acc[i][j][1], acc[i][j][2], acc[i][j][3]};
            *reinterpret_cast<float4*>(myslot + (i * 8 + j) * 512 + tid * 4) = p;
        }
    __threadfence();
    __syncthreads();
    if (tid == 0) role = atomicAdd(&g_cnt[tile], 1);
    __syncthreads();
    if (role == 0) return;               // first finisher: partial published
    if (tid == 0) g_cnt[tile] = 0;       // reset for the next graph replay
    __threadfence();                     // order partner-slot loads after atomic

    // 2) second finisher: combine both partials and write the output
    const float* oslot = g_part + ((size_t)tile * 2 + (1 - split)) * (TM * TN);
    float ax = fmaxf(__uint_as_float(g_amax[0]), 1e-12f);
    float aw = fmaxf(__uint_as_float(g_amax[1]), 1e-12f);
    float alpha = __fdiv_rn(ax * aw, 7225344.0f);  // QUANT_RANGE^2
    int er = lane >> 2;
    int c2 = (lane & 3) * 2;
    float bcache[8][2];
    #pragma unroll
    for (int j = 0; j < 8; ++j) {
        bcache[j][0] = bias[n0 + noff + j * 8 + c2];
        bcache[j][1] = bias[n0 + noff + j * 8 + c2 + 1];
    }
    #pragma unroll
    for (int i = 0; i < 4; ++i) {
        int gm = m0 + moff + i * 16 + er;
        float* row0 = out + (size_t)gm * N_DIM + n0 + noff;
        float* row1 = row0 + (size_t)8 * N_DIM;
        #pragma unroll
        for (int j = 0; j < 8; ++j) {
            float4 oth = *reinterpret_cast<const float4*>(oslot + (i * 8 + j) * 512 + tid * 4);
            // fp add (RN) is commutative bitwise -> deterministic either way
            float sx = acc[i][j][0] + oth.x;
            float sy = acc[i][j][1] + oth.y;
            float sz = acc[i][j][2] + oth.z;
            float sw = acc[i][j][3] + oth.w;
            int col = j * 8 + c2;
            float2 v0 = {alpha * sx + bcache[j][0], alpha * sy + bcache[j][1]};
            float2 v1 = {alpha * sz + bcache[j][0], alpha * sw + bcache[j][1]};
            *reinterpret_cast<float2*>(row0 + col) = v0;
            *reinterpret_cast<float2*>(row1 + col) = v1;
        }
    }
}

// ---------------- launcher ---------------------------------------------------
// Exactly 4 launches; k_gemm at launch index 3 (the slot ncu captures).
extern "C" void kernel_launch(void* const* d_in, const int* in_sizes, int n_in,
                              void* d_out, int out_size) {
    const float* x    = (const float*)d_in[0];
    const float* w    = (const float*)d_in[1];
    const float* bias = (const float*)d_in[2];
    float* out        = (float*)d_out;
    int nx = in_sizes[0];

    cudaFuncSetAttribute(k_gemm, cudaFuncAttributeMaxDynamicSharedMemorySize, SMEM_BYTES);
    cudaFuncSetAttribute(k_gemm, cudaFuncAttributePreferredSharedMemoryCarveout,
                         cudaSharedmemCarveoutMaxShared);

    k_amax2<<<2048, 256>>>(x, w, nx, 1024);                 // launch 0
    k_quant<<<(M_DIM * K_DIM / 16) / 256, 256>>>(x, 0);     // launch 1
    k_quant<<<(N_DIM * K_DIM / 16) / 256, 256>>>(w, 1);     // launch 2

    int grid = 2 * (M_DIM / TM) * (N_DIM / TN);   // 2048 (split-K=2, pairs adjacent)
    k_gemm<<<grid, THREADS, SMEM_BYTES>>>(bias, out);       // launch 3
}

// round 11
// speedup vs baseline: 1.1816x; 1.1507x over previous
#include <cuda_runtime.h>
#include <cuda_bf16.h>
#include <cuda_fp8.h>
#include <cstdint>

// Problem dims (fixed by the dataset)
#define M_DIM 4096
#define N_DIM 4096
#define K_DIM 4096

// ---------------- scratch (device globals; no allocations allowed) ----------
// g_amax starts zero (BSS); atomicMax over identical inputs is idempotent
// across graph replays.
__device__ __align__(1024) __nv_bfloat16 g_dx[(size_t)M_DIM * K_DIM];
__device__ __align__(1024) __nv_bfloat16 g_dw[(size_t)N_DIM * K_DIM];
__device__ unsigned int g_amax[2];

// ---------------- PTX helpers ----------------------------------------------
__device__ __forceinline__ uint32_t smem_u32(const void* p) {
    uint32_t a;
    asm("{ .reg .u64 t; cvta.to.shared.u64 t, %1; cvt.u32.u64 %0, t; }"
        : "=r"(a) : "l"(p));
    return a;
}

#define CP16(dst, src) \
    asm volatile("cp.async.cg.shared.global [%0], [%1], 16;" :: "r"((uint32_t)(dst)), "l"(src) : "memory")
#define CP_COMMIT() asm volatile("cp.async.commit_group;" ::: "memory")
#define CP_WAIT1()  asm volatile("cp.async.wait_group 1;" ::: "memory")

__device__ __forceinline__ void ldsm4(uint32_t* r, uint32_t addr) {
    asm volatile("ldmatrix.sync.aligned.m8n8.x4.shared.b16 {%0,%1,%2,%3}, [%4];"
                 : "=r"(r[0]), "=r"(r[1]), "=r"(r[2]), "=r"(r[3]) : "r"(addr));
}

__device__ __forceinline__ void mma16816(float* d, const uint32_t* a, const uint32_t* b) {
    asm volatile(
        "mma.sync.aligned.m16n8k16.row.col.f32.bf16.bf16.f32 "
        "{%0,%1,%2,%3}, {%4,%5,%6,%7}, {%8,%9}, {%0,%1,%2,%3};"
        : "+f"(d[0]), "+f"(d[1]), "+f"(d[2]), "+f"(d[3])
        : "r"(a[0]), "r"(a[1]), "r"(a[2]), "r"(a[3]), "r"(b[0]), "r"(b[1]));
}

// ---------------- launch 0: global amax of BOTH tensors ---------------------
__global__ void k_amax2(const float* __restrict__ x, const float* __restrict__ w,
                        int n_each, int half) {
    int slot = (blockIdx.x >= half) ? 1 : 0;
    const float* p = slot ? w : x;
    int b = slot ? (blockIdx.x - half) : blockIdx.x;

    float m = 0.0f;
    int i = b * blockDim.x + threadIdx.x;
    int stride = half * blockDim.x;
    const float4* p4 = reinterpret_cast<const float4*>(p);
    int n4 = n_each >> 2;
    for (int j = i; j < n4; j += stride) {
        float4 v = p4[j];
        m = fmaxf(m, fmaxf(fmaxf(fabsf(v.x), fabsf(v.y)), fmaxf(fabsf(v.z), fabsf(v.w))));
    }
    #pragma unroll
    for (int o = 16; o > 0; o >>= 1)
        m = fmaxf(m, __shfl_xor_sync(0xFFFFFFFFu, m, o));
    if ((threadIdx.x & 31) == 0)
        atomicMax(&g_amax[slot], __float_as_uint(m));
}

// ---------------- launches 1,2: quantize->dequantize to bf16 ----------------
// One thread per 16-element NVFP4 block. Exact replication of reference math.
__global__ void __launch_bounds__(256) k_quant(const float* __restrict__ src, int slot) {
    __nv_bfloat16* __restrict__ dst = (slot == 0) ? g_dx : g_dw;
    float am = fmaxf(__uint_as_float(g_amax[slot]), 1e-12f);
    float gs = __fdiv_rn(2688.0f, am);          // QUANT_RANGE / amax (IEEE RN)
    size_t blk = (size_t)blockIdx.x * blockDim.x + threadIdx.x;

    const float4* s4 = reinterpret_cast<const float4*>(src) + blk * 4;
    float4 f0 = s4[0], f1 = s4[1], f2 = s4[2], f3 = s4[3];
    float v[16] = {f0.x, f0.y, f0.z, f0.w, f1.x, f1.y, f1.z, f1.w,
                   f2.x, f2.y, f2.z, f2.w, f3.x, f3.y, f3.z, f3.w};

    float bm = 0.0f;
    #pragma unroll
    for (int i = 0; i < 16; ++i) bm = fmaxf(bm, fabsf(v[i]));

    float t = __fdiv_rn(bm * gs, 6.0f);
    __nv_fp8_storage_t s8 = __nv_cvt_float_to_fp8(t, __NV_SATFINITE, __NV_E4M3);
    float sf = __half2float((__half)__nv_cvt_fp8_to_halfraw(s8, __NV_E4M3));
    float ratio = __fdiv_rn(gs, fmaxf(sf, 1e-12f));

    union { __nv_bfloat16 h[16]; uint4 u[2]; } pk;
    #pragma unroll
    for (int i = 0; i < 16; ++i) {
        float a = fabsf(v[i]) * ratio;
        float stp = (a < 2.0f) ? 0.5f : ((a < 4.0f) ? 1.0f : 2.0f);
        float inv = (a < 2.0f) ? 2.0f : ((a < 4.0f) ? 1.0f : 0.5f);
        float q = fminf(rintf(a * inv) * stp, 6.0f);  // RTNE, same grid as ref
        float dq = (v[i] < 0.0f ? -q : q) * sf;       // <=6 sig bits: exact in bf16
        pk.h[i] = __float2bfloat16(dq);
    }
    uint4* d = reinterpret_cast<uint4*>(dst + blk * 16);
    d[0] = pk.u[0];
    d[1] = pk.u[1];
}

// ---------------- launch 3: bf16 mma.sync GEMM (2 CTAs/SM, 4 warps) ---------
// out[m,n] = alpha * sum_k dx[m,k]*dw[n,k] + bias[n]
// Tile 128x128x64, 128 threads (4 warps, warp tile 64x64), 3 stages.
// cp.async issues are interleaved into the ks blocks so the LDGSTS burst sits
// in the ldsm->mma dependency shadow instead of starving the tensor pipe.
// (R7 configuration — best measured: GEMM 319us @ tensor 81.7%.)
#define TM 128
#define TN 128
#define TK 64
#define STAGES 3
#define THREADS 128
#define A_STG (TM * TK * 2)     // 16384 B
#define B_STG (TN * TK * 2)     // 16384 B
#define STG   (A_STG + B_STG)   // 32768 B
#define SMEM_BYTES (STAGES * STG)   // 98304 -> 2 CTAs/SM
#define GJUMP ((size_t)16 * K_DIM * 2)   // 16 global rows between a thread's chunks

__global__ void __launch_bounds__(THREADS, 2) k_gemm(const float* __restrict__ bias,
                                                     float* __restrict__ out) {
    extern __shared__ char smem[];
    uint32_t sb = smem_u32(smem);

    int tid  = threadIdx.x;
    int wid  = tid >> 5;
    int lane = tid & 31;

    // grouped rasterization (GROUP_M = 8) for L2 reuse
    const int NT = N_DIM / TN;           // 32
    const int GM = 8;
    int bid = blockIdx.x;
    int tpg = GM * NT;                   // 256
    int g  = bid / tpg;
    int r  = bid % tpg;
    int mt = g * GM + (r % GM);
    int nt = r / GM;
    int m0 = mt * TM, n0 = nt * TN;

    int moff = (wid & 1) * 64;           // 2 warps in M
    int noff = (wid >> 1) * 64;          // 2 warps in N

    // ---- cp.async: 8 A + 8 B chunks per thread via row-stride-16 jumps -----
    int prow = tid >> 3;                 // 0..15
    int pc   = tid & 7;                  // 16B chunk in 128B row
    const char* abase = (const char*)g_dx + ((size_t)(m0 + prow) * K_DIM + pc * 8) * 2;
    const char* bbase = (const char*)g_dw + ((size_t)(n0 + prow) * K_DIM + pc * 8) * 2;
    // rows prow+16j are congruent mod 8 -> same swizzle XOR for all j
    uint32_t asoff = (uint32_t)(prow * 128 + ((pc ^ (prow & 7)) << 4));
    uint32_t bsoff = asoff + A_STG;

    // ---- ldmatrix row bases -------------------------------------------------
    int a_rl = lane & 15;
    int a_ko = lane >> 4;
    int b_rl = (lane & 7) | ((lane >> 4) << 3);
    int b_ko = (lane >> 3) & 1;

    uint32_t arow[4]; int arx[4];
    #pragma unroll
    for (int t = 0; t < 4; ++t) {
        int rr = moff + t * 16 + a_rl;
        arow[t] = (uint32_t)(rr * 128);
        arx[t]  = rr & 7;
    }
    uint32_t brow[4]; int brx[4];
    #pragma unroll
    for (int t = 0; t < 4; ++t) {
        int rr = noff + t * 16 + b_rl;
        brow[t] = (uint32_t)(rr * 128 + A_STG);
        brx[t]  = rr & 7;
    }

    float acc[4][8][4];                  // [m16][n8][frag] = 128 regs
    #pragma unroll
    for (int i = 0; i < 4; ++i)
        #pragma unroll
        for (int j = 0; j < 8; ++j)
            #pragma unroll
            for (int q = 0; q < 4; ++q) acc[i][j][q] = 0.0f;

    // ---- prologue: fill stages 0,1 -----------------------------------------
    #pragma unroll
    for (int p = 0; p < STAGES - 1; ++p) {
        size_t koff = (size_t)p * 128;   // TK*2 bytes
        uint32_t d0 = sb + p * STG;
        #pragma unroll
        for (int j = 0; j < 8; ++j) CP16(d0 + asoff + j * 2048, abase + j * GJUMP + koff);
        #pragma unroll
        for (int j = 0; j < 8; ++j) CP16(d0 + bsoff + j * 2048, bbase + j * GJUMP + koff);
        CP_COMMIT();
    }

    const int NKT = K_DIM / TK;          // 64
    int s_use = 0, s_pf = STAGES - 1;
    for (int kt = 0; kt < NKT; ++kt) {
        CP_WAIT1();
        __syncthreads();

        int pf = kt + STAGES - 1;
        bool do_pf = (pf < NKT);
        size_t koff = (size_t)pf * 128;
        uint32_t d0 = sb + s_pf * STG;
        uint32_t bA = sb + s_use * STG;

        // ks blocks with cp.async interleaved into the ldsm->mma latency gap:
        // ks0 issues A chunks 0-3, ks1 A chunks 4-7, ks2 B 0-3, ks3 B 4-7.
        #pragma unroll
        for (int ks = 0; ks < 4; ++ks) {
            uint32_t a[4][4], b[4][4];
            #pragma unroll
            for (int t = 0; t < 4; ++t)
                ldsm4(a[t], bA + arow[t] + (uint32_t)((((ks * 2 + a_ko) ^ arx[t])) << 4));
            #pragma unroll
            for (int t = 0; t < 4; ++t)
                ldsm4(b[t], bA + brow[t] + (uint32_t)((((ks * 2 + b_ko) ^ brx[t])) << 4));

            if (do_pf) {
                if (ks < 2) {
                    #pragma unroll
                    for (int j = 0; j < 4; ++j) {
                        int c = ks * 4 + j;
                        CP16(d0 + asoff + c * 2048, abase + c * GJUMP + koff);
                    }
                } else {
                    #pragma unroll
                    for (int j = 0; j < 4; ++j) {
                        int c = (ks - 2) * 4 + j;
                        CP16(d0 + bsoff + c * 2048, bbase + c * GJUMP + koff);
                    }
                }
            }

            #pragma unroll
            for (int i = 0; i < 4; ++i)
                #pragma unroll
                for (int j = 0; j < 8; ++j)
                    mma16816(acc[i][j], a[i], &b[j >> 1][(j & 1) * 2]);
        }
        CP_COMMIT();                     // always commit (keeps wait_group count)

        if (++s_use == STAGES) s_use = 0;
        if (++s_pf  == STAGES) s_pf  = 0;
    }

    // ---- epilogue: alpha * acc + bias, direct fp32 stores ------------------
    float ax = fmaxf(__uint_as_float(g_amax[0]), 1e-12f);
    float aw = fmaxf(__uint_as_float(g_amax[1]), 1e-12f);
    float alpha = __fdiv_rn(ax * aw, 7225344.0f);  // QUANT_RANGE^2
    int er = lane >> 2;
    int c2 = (lane & 3) * 2;
    float bcache[8][2];
    #pragma unroll
    for (int j = 0; j < 8; ++j) {
        bcache[j][0] = bias[n0 + noff + j * 8 + c2];
        bcache[j][1] = bias[n0 + noff + j * 8 + c2 + 1];
    }
    #pragma unroll
    for (int i = 0; i < 4; ++i) {
        int gm = m0 + moff + i * 16 + er;
        float* row0 = out + (size_t)gm * N_DIM + n0 + noff;
        float* row1 = row0 + (size_t)8 * N_DIM;
        #pragma unroll
        for (int j = 0; j < 8; ++j) {
            int col = j * 8 + c2;
            float2 v0 = {alpha * acc[i][j][0] + bcache[j][0], alpha * acc[i][j][1] + bcache[j][1]};
            float2 v1 = {alpha * acc[i][j][2] + bcache[j][0], alpha * acc[i][j][3] + bcache[j][1]};
            *reinterpret_cast<float2*>(row0 + col) = v0;
            *reinterpret_cast<float2*>(row1 + col) = v1;
        }
    }
}

// ---------------- launcher ---------------------------------------------------
// Exactly 4 launches; k_gemm at launch index 3 (the slot ncu captures).
extern "C" void kernel_launch(void* const* d_in, const int* in_sizes, int n_in,
                              void* d_out, int out_size) {
    const float* x    = (const float*)d_in[0];
    const float* w    = (const float*)d_in[1];
    const float* bias = (const float*)d_in[2];
    float* out        = (float*)d_out;
    int nx = in_sizes[0];

    cudaFuncSetAttribute(k_gemm, cudaFuncAttributeMaxDynamicSharedMemorySize, SMEM_BYTES);
    cudaFuncSetAttribute(k_gemm, cudaFuncAttributePreferredSharedMemoryCarveout,
                         cudaSharedmemCarveoutMaxShared);

    k_amax2<<<2048, 256>>>(x, w, nx, 1024);                 // launch 0
    k_quant<<<(M_DIM * K_DIM / 16) / 256, 256>>>(x, 0);     // launch 1
    k_quant<<<(N_DIM * K_DIM / 16) / 256, 256>>>(w, 1);     // launch 2

    int grid = (M_DIM / TM) * (N_DIM / TN);   // 1024
    k_gemm<<<grid, THREADS, SMEM_BYTES>>>(bias, out);       // launch 3
}